// round 1
// baseline (speedup 1.0000x reference)
#include <cuda_runtime.h>
#include <math.h>

#define BD 4
#define SD 4096
#define HD 32
#define PD 64
#define ND 64
#define BLK 64
#define NCH (SD / BLK)   // 64 chunks
#define SMS 68           // smem row stride (floats): conflict-free + float4 aligned

// Scratch: chunk states [b][h][chunk][n][p] (in-place converted to incoming states by k2)
__device__ float g_states[(size_t)BD * HD * NCH * ND * PD];
__device__ float g_atot[BD * HD * NCH];

// ---------------------------------------------------------------------------
// K1: per (b,h,chunk): states[n][p] = sum_l B[l][n] * exp(cumA[63]-cumA[l]) * X[l][p]
// ---------------------------------------------------------------------------
__global__ __launch_bounds__(256)
void k1_states(const float* __restrict__ A, const float* __restrict__ B,
               const float* __restrict__ X) {
  const int ch = blockIdx.x, h = blockIdx.y, b = blockIdx.z;
  __shared__ float sB[BLK * SMS];
  __shared__ float sX[BLK * SMS];
  __shared__ float cum[BLK];
  __shared__ float dec[BLK];
  const int tid = threadIdx.x;

  const float* Ap = A + ((size_t)b * SD + (size_t)ch * BLK) * HD + h;
  if (tid < BLK) cum[tid] = Ap[(size_t)tid * HD];

  const size_t rowoff = ((size_t)b * SD + (size_t)ch * BLK) * HD + h;
  const float* Bp = B + rowoff * ND;
  const float* Xp = X + rowoff * PD;
  for (int i = tid; i < BLK * ND; i += 256) {
    int l = i >> 6, j = i & 63;
    sB[l * SMS + j] = Bp[(size_t)l * HD * ND + j];
    sX[l * SMS + j] = Xp[(size_t)l * HD * PD + j];
  }
  __syncthreads();
  if (tid == 0) {
    float run = 0.f;
    for (int l = 0; l < BLK; l++) { run += cum[l]; cum[l] = run; }
  }
  __syncthreads();
  const float total = cum[BLK - 1];
  if (tid < BLK) dec[tid] = expf(total - cum[tid]);
  if (tid == 0) g_atot[((size_t)b * HD + h) * NCH + ch] = total;
  __syncthreads();
  for (int i = tid; i < BLK * ND; i += 256) {
    sB[(i >> 6) * SMS + (i & 63)] *= dec[i >> 6];
  }
  __syncthreads();

  const int ty = tid >> 4, tx = tid & 15;
  float acc[4][4] = {};
#pragma unroll 8
  for (int l = 0; l < BLK; l++) {
    float4 bq = *(const float4*)&sB[l * SMS + 4 * ty];
    float4 xq = *(const float4*)&sX[l * SMS + 4 * tx];
    float bv[4] = {bq.x, bq.y, bq.z, bq.w};
    float xv[4] = {xq.x, xq.y, xq.z, xq.w};
#pragma unroll
    for (int r = 0; r < 4; r++)
#pragma unroll
      for (int c = 0; c < 4; c++) acc[r][c] += bv[r] * xv[c];
  }

  float* out = g_states + (((size_t)b * HD + h) * NCH + ch) * (size_t)(ND * PD);
#pragma unroll
  for (int r = 0; r < 4; r++) {
    *(float4*)&out[(size_t)(4 * ty + r) * PD + 4 * tx] =
        make_float4(acc[r][0], acc[r][1], acc[r][2], acc[r][3]);
  }
}

// ---------------------------------------------------------------------------
// K2: per (b,h): in-place scan over chunks:
//   tmp = states[c]; states[c] = run; run = run*exp(Atot[c]) + tmp
// grid: (BD*HD*8) blocks, each handles 512 of the 4096 state elements
// ---------------------------------------------------------------------------
__global__ __launch_bounds__(256)
void k2_scan() {
  const int bh = blockIdx.x >> 3;
  const int seg = blockIdx.x & 7;
  __shared__ float dec[NCH];
  const int tid = threadIdx.x;
  if (tid < NCH) dec[tid] = expf(g_atot[(size_t)bh * NCH + tid]);
  __syncthreads();
  float* st = g_states + (size_t)bh * NCH * ND * PD + seg * 512 + tid;
  float run0 = 0.f, run1 = 0.f;
#pragma unroll 4
  for (int c = 0; c < NCH; c++) {
    const float d = dec[c];
    float t0 = st[0];
    float t1 = st[256];
    st[0] = run0;
    st[256] = run1;
    run0 = run0 * d + t0;
    run1 = run1 * d + t1;
    st += ND * PD;
  }
}

// ---------------------------------------------------------------------------
// K3: per (b,h,chunk):
//   Cexp[i][n] = C[i][n]*exp(cum[i]);  BexpT[n][j] = B[j][n]*exp(-cum[j])
//   S = tril(Cexp @ BexpT);  Y = S @ X + Cexp @ state_in
// ---------------------------------------------------------------------------
__global__ __launch_bounds__(256)
void k3_y(const float* __restrict__ A, const float* __restrict__ B,
          const float* __restrict__ C, const float* __restrict__ X,
          float* __restrict__ Y) {
  const int ch = blockIdx.x, h = blockIdx.y, b = blockIdx.z;
  extern __shared__ float smem[];
  float* sC  = smem;                 // Cexp [i][n]
  float* sBT = sC + BLK * SMS;       // BexpT [n][j]
  float* sX  = sBT + BLK * SMS;      // X [j][p]
  float* sSI = sX + BLK * SMS;       // state_in [n][p]
  float* sS  = sSI + BLK * SMS;      // S [i][j]
  __shared__ float cum[BLK];
  __shared__ float rs[BLK], rsi[BLK];
  const int tid = threadIdx.x;

  const float* Ap = A + ((size_t)b * SD + (size_t)ch * BLK) * HD + h;
  if (tid < BLK) cum[tid] = Ap[(size_t)tid * HD];

  const size_t rowoff = ((size_t)b * SD + (size_t)ch * BLK) * HD + h;
  const float* Bp = B + rowoff * ND;
  const float* Cp = C + rowoff * ND;
  const float* Xp = X + rowoff * PD;
  const float* SIp = g_states + (((size_t)b * HD + h) * NCH + ch) * (size_t)(ND * PD);
  for (int i = tid; i < BLK * ND; i += 256) {
    int l = i >> 6, j = i & 63;
    sC[l * SMS + j]  = Cp[(size_t)l * HD * ND + j];
    sBT[j * SMS + l] = Bp[(size_t)l * HD * ND + j];   // transpose B
    sX[l * SMS + j]  = Xp[(size_t)l * HD * PD + j];
    sSI[l * SMS + j] = SIp[i];
  }
  __syncthreads();
  if (tid == 0) {
    float run = 0.f;
    for (int l = 0; l < BLK; l++) { run += cum[l]; cum[l] = run; }
  }
  __syncthreads();
  if (tid < BLK) { rs[tid] = expf(cum[tid]); rsi[tid] = expf(-cum[tid]); }
  __syncthreads();
  for (int i = tid; i < BLK * ND; i += 256) {
    int l = i >> 6, j = i & 63;
    sC[l * SMS + j]  *= rs[l];
    sBT[l * SMS + j] *= rsi[j];
  }
  __syncthreads();

  const int ty = tid >> 4, tx = tid & 15;

  // S = tril(Cexp @ BexpT)
  float acc[4][4] = {};
#pragma unroll 8
  for (int n = 0; n < ND; n++) {
    float cv[4];
#pragma unroll
    for (int r = 0; r < 4; r++) cv[r] = sC[(size_t)(4 * ty + r) * SMS + n];
    float4 bq = *(const float4*)&sBT[n * SMS + 4 * tx];
    float bv[4] = {bq.x, bq.y, bq.z, bq.w};
#pragma unroll
    for (int r = 0; r < 4; r++)
#pragma unroll
      for (int c = 0; c < 4; c++) acc[r][c] += cv[r] * bv[c];
  }
#pragma unroll
  for (int r = 0; r < 4; r++) {
    const int i = 4 * ty + r;
#pragma unroll
    for (int c = 0; c < 4; c++) {
      const int j = 4 * tx + c;
      if (j > i) acc[r][c] = 0.f;
    }
    *(float4*)&sS[(size_t)i * SMS + 4 * tx] =
        make_float4(acc[r][0], acc[r][1], acc[r][2], acc[r][3]);
  }
  __syncthreads();

  // Y = S @ X + Cexp @ state_in
  float y[4][4] = {};
#pragma unroll 8
  for (int j = 0; j < BLK; j++) {
    float sv[4];
#pragma unroll
    for (int r = 0; r < 4; r++) sv[r] = sS[(size_t)(4 * ty + r) * SMS + j];
    float4 xq = *(const float4*)&sX[j * SMS + 4 * tx];
    float xv[4] = {xq.x, xq.y, xq.z, xq.w};
#pragma unroll
    for (int r = 0; r < 4; r++)
#pragma unroll
      for (int c = 0; c < 4; c++) y[r][c] += sv[r] * xv[c];
  }
#pragma unroll 8
  for (int n = 0; n < ND; n++) {
    float cv[4];
#pragma unroll
    for (int r = 0; r < 4; r++) cv[r] = sC[(size_t)(4 * ty + r) * SMS + n];
    float4 sq = *(const float4*)&sSI[n * SMS + 4 * tx];
    float sv[4] = {sq.x, sq.y, sq.z, sq.w};
#pragma unroll
    for (int r = 0; r < 4; r++)
#pragma unroll
      for (int c = 0; c < 4; c++) y[r][c] += cv[r] * sv[c];
  }

  float* Yp = Y + rowoff * PD;
#pragma unroll
  for (int r = 0; r < 4; r++) {
    *(float4*)&Yp[(size_t)(4 * ty + r) * HD * PD + 4 * tx] =
        make_float4(y[r][0], y[r][1], y[r][2], y[r][3]);
  }
}

// ---------------------------------------------------------------------------
extern "C" void kernel_launch(void* const* d_in, const int* in_sizes, int n_in,
                              void* d_out, int out_size) {
  const float* X = (const float*)d_in[0];
  const float* A = (const float*)d_in[1];
  const float* B = (const float*)d_in[2];
  const float* C = (const float*)d_in[3];
  float* Y = (float*)d_out;

  const int smem_k3 = 5 * BLK * SMS * sizeof(float);  // 87040 bytes
  cudaFuncSetAttribute(k3_y, cudaFuncAttributeMaxDynamicSharedMemorySize, smem_k3);

  dim3 grid(NCH, HD, BD);
  k1_states<<<grid, 256>>>(A, B, X);
  k2_scan<<<BD * HD * 8, 256>>>();
  k3_y<<<grid, 256, smem_k3>>>(A, B, C, X, Y);
}

// round 8
// speedup vs baseline: 1.3181x; 1.3181x over previous
#include <cuda_runtime.h>
#include <cuda_bf16.h>
#include <mma.h>
#include <math.h>
#include <stdint.h>

using namespace nvcuda;

#define BD 4
#define SD 4096
#define HD 32
#define PD 64
#define ND 64
#define BLK 64
#define NCH 64
#define LDS_ 72   // smem tile leading dim (elements); %8==0 for wmma, odd/8 for banks

// Scratch: chunk states [b][h][chunk][n][p]; k2 converts in-place to incoming states
__device__ float g_states[(size_t)BD * HD * NCH * ND * PD];
__device__ float g_atot[BD * HD * NCH];

__device__ __forceinline__ void bsplit(float v, __nv_bfloat16& h, __nv_bfloat16& l) {
  h = __float2bfloat16_rn(v);
  l = __float2bfloat16_rn(v - __bfloat162float(h));
}

typedef wmma::fragment<wmma::matrix_a, 16, 16, 16, __nv_bfloat16, wmma::row_major> FragAR;
typedef wmma::fragment<wmma::matrix_a, 16, 16, 16, __nv_bfloat16, wmma::col_major> FragAC;
typedef wmma::fragment<wmma::matrix_b, 16, 16, 16, __nv_bfloat16, wmma::row_major> FragBR;
typedef wmma::fragment<wmma::matrix_b, 16, 16, 16, __nv_bfloat16, wmma::col_major> FragBC;
typedef wmma::fragment<wmma::accumulator, 16, 16, 16, float> FragC;

// ---------------------------------------------------------------------------
// Shared cumsum of A over the chunk (64 values) -> s_cum
// ---------------------------------------------------------------------------
__device__ __forceinline__ void chunk_cumsum(const float* Ap, float* s_cum, int tid) {
  if (tid < 64) {
    float v = Ap[(size_t)tid * HD];
#pragma unroll
    for (int o = 1; o < 32; o <<= 1) {
      float t = __shfl_up_sync(0xffffffffu, v, o);
      if ((tid & 31) >= o) v += t;
    }
    s_cum[tid] = v;
  }
  __syncthreads();
  if (tid >= 32 && tid < 64) s_cum[tid] += s_cum[31];
  __syncthreads();
}

// ---------------------------------------------------------------------------
// K1: per (b,h,chunk): states[n][p] = sum_l Bdec[l][n] * X[l][p]
//   A-op = Bdec^T (col_major view of Bdec [l][n]), B-op = X [l][p] row-major
// smem: sBh sBl sXh sXl (each 64 x 72 bf16)
// ---------------------------------------------------------------------------
__global__ __launch_bounds__(256)
void k1_states(const float* __restrict__ A, const float* __restrict__ B,
               const float* __restrict__ X) {
  extern __shared__ char sm1[];
  __nv_bfloat16* sBh = (__nv_bfloat16*)sm1;
  __nv_bfloat16* sBl = sBh + 64 * LDS_;
  __nv_bfloat16* sXh = sBl + 64 * LDS_;
  __nv_bfloat16* sXl = sXh + 64 * LDS_;
  __shared__ float s_cum[BLK];
  __shared__ float s_dec[BLK];
  const int tid = threadIdx.x;
  const int ch = blockIdx.x, h = blockIdx.y, b = blockIdx.z;

  const float* Ap = A + ((size_t)b * SD + (size_t)ch * BLK) * HD + h;
  chunk_cumsum(Ap, s_cum, tid);
  const float total = s_cum[63];
  if (tid < 64) s_dec[tid] = expf(total - s_cum[tid]);
  if (tid == 0) g_atot[((size_t)b * HD + h) * NCH + ch] = total;
  __syncthreads();

  const size_t rowoff = ((size_t)b * SD + (size_t)ch * BLK) * HD + h;
  const float* Bp = B + rowoff * ND;
  const float* Xp = X + rowoff * PD;
  for (int i = tid; i < 2048; i += 256) {
    const int l = i >> 5, cp = (i & 31) << 1;
    const float2 bv = *(const float2*)&Bp[(size_t)l * HD * ND + cp];
    const float2 xv = *(const float2*)&Xp[(size_t)l * HD * PD + cp];
    const float d = s_dec[l];
    bsplit(bv.x * d, sBh[l * LDS_ + cp], sBl[l * LDS_ + cp]);
    bsplit(bv.y * d, sBh[l * LDS_ + cp + 1], sBl[l * LDS_ + cp + 1]);
    bsplit(xv.x, sXh[l * LDS_ + cp], sXl[l * LDS_ + cp]);
    bsplit(xv.y, sXh[l * LDS_ + cp + 1], sXl[l * LDS_ + cp + 1]);
  }
  __syncthreads();

  const int w = tid >> 5;
  const int r = w >> 1;            // n block (16 output rows)
  const int cb = (w & 1) * 2;      // first p block
  FragC acc[2];
  wmma::fill_fragment(acc[0], 0.f);
  wmma::fill_fragment(acc[1], 0.f);
#pragma unroll
  for (int k0 = 0; k0 < 4; k0++) {
    FragAC ah, al;  // (n,l) at l*LDS_+n  == col_major with ldm=LDS_
    wmma::load_matrix_sync(ah, &sBh[k0 * 16 * LDS_ + r * 16], LDS_);
    wmma::load_matrix_sync(al, &sBl[k0 * 16 * LDS_ + r * 16], LDS_);
#pragma unroll
    for (int ct = 0; ct < 2; ct++) {
      FragBR bh, bl;
      wmma::load_matrix_sync(bh, &sXh[k0 * 16 * LDS_ + (cb + ct) * 16], LDS_);
      wmma::load_matrix_sync(bl, &sXl[k0 * 16 * LDS_ + (cb + ct) * 16], LDS_);
      wmma::mma_sync(acc[ct], ah, bh, acc[ct]);
      wmma::mma_sync(acc[ct], ah, bl, acc[ct]);
      wmma::mma_sync(acc[ct], al, bh, acc[ct]);
    }
  }
  float* out = g_states + (((size_t)b * HD + h) * NCH + ch) * (size_t)(ND * PD);
#pragma unroll
  for (int ct = 0; ct < 2; ct++)
    wmma::store_matrix_sync(&out[(size_t)r * 16 * PD + (cb + ct) * 16], acc[ct],
                            PD, wmma::mem_row_major);
}

// ---------------------------------------------------------------------------
// K2: per (b,h): in-place scan over chunks (fp32, exact)
// ---------------------------------------------------------------------------
__global__ __launch_bounds__(256)
void k2_scan() {
  const int bh = blockIdx.x >> 3;
  const int seg = blockIdx.x & 7;
  __shared__ float dec[NCH];
  const int tid = threadIdx.x;
  if (tid < NCH) dec[tid] = expf(g_atot[(size_t)bh * NCH + tid]);
  __syncthreads();
  float* st = g_states + (size_t)bh * NCH * ND * PD + seg * 512 + tid;
  float run0 = 0.f, run1 = 0.f;
#pragma unroll 4
  for (int c = 0; c < NCH; c++) {
    const float d = dec[c];
    float t0 = st[0];
    float t1 = st[256];
    st[0] = run0;
    st[256] = run1;
    run0 = run0 * d + t0;
    run1 = run1 * d + t1;
    st += ND * PD;
  }
}

// ---------------------------------------------------------------------------
// K3: per (b,h,chunk):
//   GEMM1: Sraw = Cexp @ Bexp^T  (L folded in);  mask tril -> split S
//   GEMM2: Y = S @ X + Cexp @ SI
// smem tiles (bf16 64x72 = 9216B each):
//   Ch, Cl, Xh, Xl, SIh, SIl, Bh, Bl, Sh, Sl
//   (Bh+Bl reused as fp32 Sraw [64x72] after GEMM1)
// ---------------------------------------------------------------------------
__global__ __launch_bounds__(256)
void k3_y(const float* __restrict__ A, const float* __restrict__ B,
          const float* __restrict__ C, const float* __restrict__ X,
          float* __restrict__ Y) {
  extern __shared__ char sm3[];
  __nv_bfloat16* sCh  = (__nv_bfloat16*)sm3;
  __nv_bfloat16* sCl  = sCh + 64 * LDS_;
  __nv_bfloat16* sXh  = sCl + 64 * LDS_;
  __nv_bfloat16* sXl  = sXh + 64 * LDS_;
  __nv_bfloat16* sSIh = sXl + 64 * LDS_;
  __nv_bfloat16* sSIl = sSIh + 64 * LDS_;
  __nv_bfloat16* sBh  = sSIl + 64 * LDS_;
  __nv_bfloat16* sBl  = sBh + 64 * LDS_;
  __nv_bfloat16* sSh  = sBl + 64 * LDS_;
  __nv_bfloat16* sSl  = sSh + 64 * LDS_;
  float* sSf = (float*)sBh;  // 64x72 fp32 overlays Bh+Bl (exactly 18432 B)
  __shared__ float s_cum[BLK];
  __shared__ float s_rs[BLK], s_rsi[BLK];
  const int tid = threadIdx.x;
  const int ch = blockIdx.x, h = blockIdx.y, b = blockIdx.z;

  const float* Ap = A + ((size_t)b * SD + (size_t)ch * BLK) * HD + h;
  chunk_cumsum(Ap, s_cum, tid);
  if (tid < 64) { s_rs[tid] = expf(s_cum[tid]); s_rsi[tid] = expf(-s_cum[tid]); }
  __syncthreads();

  const size_t rowoff = ((size_t)b * SD + (size_t)ch * BLK) * HD + h;
  const float* Bp = B + rowoff * ND;
  const float* Cp = C + rowoff * ND;
  const float* Xp = X + rowoff * PD;
  const float* SIp = g_states + (((size_t)b * HD + h) * NCH + ch) * (size_t)(ND * PD);
  for (int i = tid; i < 2048; i += 256) {
    const int r = i >> 5, cp = (i & 31) << 1;
    const float2 cv = *(const float2*)&Cp[(size_t)r * HD * ND + cp];
    const float2 bv = *(const float2*)&Bp[(size_t)r * HD * ND + cp];
    const float2 xv = *(const float2*)&Xp[(size_t)r * HD * PD + cp];
    const float2 sv = *(const float2*)&SIp[(size_t)r * PD + cp];
    const float rs = s_rs[r], rsi = s_rsi[r];
    bsplit(cv.x * rs, sCh[r * LDS_ + cp], sCl[r * LDS_ + cp]);
    bsplit(cv.y * rs, sCh[r * LDS_ + cp + 1], sCl[r * LDS_ + cp + 1]);
    bsplit(bv.x * rsi, sBh[r * LDS_ + cp], sBl[r * LDS_ + cp]);
    bsplit(bv.y * rsi, sBh[r * LDS_ + cp + 1], sBl[r * LDS_ + cp + 1]);
    bsplit(xv.x, sXh[r * LDS_ + cp], sXl[r * LDS_ + cp]);
    bsplit(xv.y, sXh[r * LDS_ + cp + 1], sXl[r * LDS_ + cp + 1]);
    bsplit(sv.x, sSIh[r * LDS_ + cp], sSIl[r * LDS_ + cp]);
    bsplit(sv.y, sSIh[r * LDS_ + cp + 1], sSIl[r * LDS_ + cp + 1]);
  }
  __syncthreads();

  const int w = tid >> 5;
  const int r = w >> 1;        // i block
  const int cb = (w & 1) * 2;  // first j/p block

  // GEMM1: Sraw = Cexp @ Bexp^T
  {
    FragC acc[2];
    wmma::fill_fragment(acc[0], 0.f);
    wmma::fill_fragment(acc[1], 0.f);
#pragma unroll
    for (int k0 = 0; k0 < 4; k0++) {
      FragAR ah, al;
      wmma::load_matrix_sync(ah, &sCh[r * 16 * LDS_ + k0 * 16], LDS_);
      wmma::load_matrix_sync(al, &sCl[r * 16 * LDS_ + k0 * 16], LDS_);
#pragma unroll
      for (int ct = 0; ct < 2; ct++) {
        FragBC bh, bl;  // Bexp^T: col_major view of Bexp [j][n]
        wmma::load_matrix_sync(bh, &sBh[(cb + ct) * 16 * LDS_ + k0 * 16], LDS_);
        wmma::load_matrix_sync(bl, &sBl[(cb + ct) * 16 * LDS_ + k0 * 16], LDS_);
        wmma::mma_sync(acc[ct], ah, bh, acc[ct]);
        wmma::mma_sync(acc[ct], ah, bl, acc[ct]);
        wmma::mma_sync(acc[ct], al, bh, acc[ct]);
      }
    }
    __syncthreads();  // everyone done READING B tiles before fp32 overwrite
#pragma unroll
    for (int ct = 0; ct < 2; ct++)
      wmma::store_matrix_sync(&sSf[r * 16 * LDS_ + (cb + ct) * 16], acc[ct],
                              LDS_, wmma::mem_row_major);
  }
  __syncthreads();

  // mask tril + split S into hi/lo bf16
  for (int e = tid; e < 4096; e += 256) {
    const int i = e >> 6, j = e & 63;
    const float v = (j <= i) ? sSf[i * LDS_ + j] : 0.f;
    bsplit(v, sSh[i * LDS_ + j], sSl[i * LDS_ + j]);
  }
  __syncthreads();

  // GEMM2: Y = S @ X + Cexp @ SI  (fused accumulation)
  {
    FragC acc[2];
    wmma::fill_fragment(acc[0], 0.f);
    wmma::fill_fragment(acc[1], 0.f);
#pragma unroll
    for (int k0 = 0; k0 < 4; k0++) {
      FragAR sh, sl, chf, clf;
      wmma::load_matrix_sync(sh, &sSh[r * 16 * LDS_ + k0 * 16], LDS_);
      wmma::load_matrix_sync(sl, &sSl[r * 16 * LDS_ + k0 * 16], LDS_);
      wmma::load_matrix_sync(chf, &sCh[r * 16 * LDS_ + k0 * 16], LDS_);
      wmma::load_matrix_sync(clf, &sCl[r * 16 * LDS_ + k0 * 16], LDS_);
#pragma unroll
      for (int ct = 0; ct < 2; ct++) {
        FragBR xh, xl, ih, il;
        wmma::load_matrix_sync(xh, &sXh[k0 * 16 * LDS_ + (cb + ct) * 16], LDS_);
        wmma::load_matrix_sync(xl, &sXl[k0 * 16 * LDS_ + (cb + ct) * 16], LDS_);
        wmma::load_matrix_sync(ih, &sSIh[k0 * 16 * LDS_ + (cb + ct) * 16], LDS_);
        wmma::load_matrix_sync(il, &sSIl[k0 * 16 * LDS_ + (cb + ct) * 16], LDS_);
        wmma::mma_sync(acc[ct], sh, xh, acc[ct]);
        wmma::mma_sync(acc[ct], sh, xl, acc[ct]);
        wmma::mma_sync(acc[ct], sl, xh, acc[ct]);
        wmma::mma_sync(acc[ct], chf, ih, acc[ct]);
        wmma::mma_sync(acc[ct], chf, il, acc[ct]);
        wmma::mma_sync(acc[ct], clf, ih, acc[ct]);
      }
    }
    float* Yp = Y + rowoff * PD;
#pragma unroll
    for (int ct = 0; ct < 2; ct++)
      wmma::store_matrix_sync(&Yp[(size_t)r * 16 * HD * PD + (cb + ct) * 16],
                              acc[ct], HD * PD, wmma::mem_row_major);
  }
}

// ---------------------------------------------------------------------------
extern "C" void kernel_launch(void* const* d_in, const int* in_sizes, int n_in,
                              void* d_out, int out_size) {
  const float* X = (const float*)d_in[0];
  const float* A = (const float*)d_in[1];
  const float* B = (const float*)d_in[2];
  const float* C = (const float*)d_in[3];
  float* Y = (float*)d_out;

  const int smem_k1 = 4 * 64 * LDS_ * sizeof(__nv_bfloat16);   // 36864
  const int smem_k3 = 10 * 64 * LDS_ * sizeof(__nv_bfloat16);  // 92160
  cudaFuncSetAttribute(k1_states, cudaFuncAttributeMaxDynamicSharedMemorySize, smem_k1);
  cudaFuncSetAttribute(k3_y, cudaFuncAttributeMaxDynamicSharedMemorySize, smem_k3);

  dim3 grid(NCH, HD, BD);
  k1_states<<<grid, 256, smem_k1>>>(A, B, X);
  k2_scan<<<BD * HD * 8, 256>>>();
  k3_y<<<grid, 256, smem_k3>>>(A, B, C, X, Y);
}